// round 1
// baseline (speedup 1.0000x reference)
#include <cuda_runtime.h>
#include <math.h>

#define DIM 1024
#define VOCAB 50257

// Scratch (no allocations allowed in kernel_launch)
__device__ float g_yk[DIM];
__device__ float g_z[DIM];

// Kernel 1: y_k = relu(filters[:,0]) except last element passes through.
__global__ void yk_kernel(const float* __restrict__ filters) {
    int j = threadIdx.x;
    float v = filters[(size_t)j * VOCAB];
    g_yk[j] = (j == DIM - 1) ? v : fmaxf(v, 0.0f);
}

// Kernel 2: one block per output row. dot(w_t[row,:], y), dot(w_h[row,:], y),
// then z[row] = t*g + (1-t)*y[row].
__global__ void __launch_bounds__(256) matvec_kernel(const float* __restrict__ w_t,
                                                     const float* __restrict__ w_h) {
    const int row = blockIdx.x;
    const int tid = threadIdx.x;

    // Each thread handles columns [4*tid, 4*tid+3]: fully coalesced float4 loads.
    float4 y = ((const float4*)g_yk)[tid];
    float4 a = ((const float4*)(w_t + (size_t)row * DIM))[tid];
    float4 b = ((const float4*)(w_h + (size_t)row * DIM))[tid];

    float dt = a.x * y.x + a.y * y.y + a.z * y.z + a.w * y.w;
    float dh = b.x * y.x + b.y * y.y + b.z * y.z + b.w * y.w;

    #pragma unroll
    for (int o = 16; o; o >>= 1) {
        dt += __shfl_xor_sync(0xffffffffu, dt, o);
        dh += __shfl_xor_sync(0xffffffffu, dh, o);
    }

    __shared__ float st[8], sh[8];
    int warp = tid >> 5, lane = tid & 31;
    if (lane == 0) { st[warp] = dt; sh[warp] = dh; }
    __syncthreads();

    if (tid == 0) {
        float T = 0.0f, H = 0.0f;
        #pragma unroll
        for (int w = 0; w < 8; w++) { T += st[w]; H += sh[w]; }
        float t = 1.0f / (1.0f + expf(-T));
        float g = fmaxf(H, 0.0f);
        float yk = g_yk[row];
        g_z[row] = t * g + (1.0f - t) * yk;
    }
}

// Kernel 3: log_softmax over the 1024-element z vector (single block).
__global__ void __launch_bounds__(DIM) softmax_kernel(float* __restrict__ out) {
    const int tid = threadIdx.x;
    const int warp = tid >> 5, lane = tid & 31;
    __shared__ float sred[32];

    float z = g_z[tid];

    // --- max reduce ---
    float m = z;
    #pragma unroll
    for (int o = 16; o; o >>= 1) m = fmaxf(m, __shfl_xor_sync(0xffffffffu, m, o));
    if (lane == 0) sred[warp] = m;
    __syncthreads();
    if (warp == 0) {
        float v = sred[lane];
        #pragma unroll
        for (int o = 16; o; o >>= 1) v = fmaxf(v, __shfl_xor_sync(0xffffffffu, v, o));
        if (lane == 0) sred[0] = v;
    }
    __syncthreads();
    float gmax = sred[0];
    __syncthreads();  // protect sred reuse

    // --- sum of exp reduce ---
    float e = expf(z - gmax);
    float s = e;
    #pragma unroll
    for (int o = 16; o; o >>= 1) s += __shfl_xor_sync(0xffffffffu, s, o);
    if (lane == 0) sred[warp] = s;
    __syncthreads();
    if (warp == 0) {
        float v = sred[lane];
        #pragma unroll
        for (int o = 16; o; o >>= 1) v += __shfl_xor_sync(0xffffffffu, v, o);
        if (lane == 0) sred[0] = v;
    }
    __syncthreads();

    out[tid] = z - gmax - logf(sred[0]);
}

extern "C" void kernel_launch(void* const* d_in, const int* in_sizes, int n_in,
                              void* d_out, int out_size) {
    // metadata order: input (int32, unused), filters, w_t, w_h
    const float* filters = (const float*)d_in[1];
    const float* w_t     = (const float*)d_in[2];
    const float* w_h     = (const float*)d_in[3];
    float* out           = (float*)d_out;

    yk_kernel<<<1, DIM>>>(filters);
    matvec_kernel<<<DIM, 256>>>(w_t, w_h);
    softmax_kernel<<<1, DIM>>>(out);
}